// round 5
// baseline (speedup 1.0000x reference)
#include <cuda_runtime.h>
#include <cuda_fp16.h>
#include <cstdint>
#include <cstddef>

#define NNODE 8192
#define DFEAT 128
#define SEC   1048576  // 8192*128

// ---------------- scratch (allocation-free __device__ globals) ----------------
__device__ __align__(16) __half g_adj16[(size_t)NNODE * NNODE]; // adj*8192 fp16 (128 MB)
__device__ __align__(16) __half g_B16[(size_t)NNODE * DFEAT];   // (h@W) fp16 row-major (2 MB)
__device__ __align__(16) float  g_H[(size_t)NNODE * DFEAT];     // raw PReLU output fp32 (4 MB)
__device__ __align__(16) float  g_sums2[2][2 * DFEAT];          // ping-pong col sum / sumsq

// ---------------- baseline-PTX helpers (sm_80-era; safe on .target sm_103) --------
__device__ __forceinline__ uint32_t smem_u32(const void* p) {
    uint32_t a;
    asm("{ .reg .u64 t; cvta.to.shared.u64 t, %1; cvt.u32.u64 %0, t; }" : "=r"(a) : "l"(p));
    return a;
}
__device__ __forceinline__ void cp16(uint32_t saddr, const void* gaddr) {
    asm volatile("cp.async.cg.shared.global [%0], [%1], 16;" :: "r"(saddr), "l"(gaddr));
}
#define CP_COMMIT() asm volatile("cp.async.commit_group;" ::: "memory")
#define CP_WAIT1()  asm volatile("cp.async.wait_group 1;" ::: "memory")

__device__ __forceinline__ void ldsm4(uint32_t& r0, uint32_t& r1, uint32_t& r2, uint32_t& r3,
                                      uint32_t a) {
    asm volatile("ldmatrix.sync.aligned.m8n8.x4.shared.b16 {%0,%1,%2,%3}, [%4];"
                 : "=r"(r0), "=r"(r1), "=r"(r2), "=r"(r3) : "r"(a));
}
__device__ __forceinline__ void ldsm4t(uint32_t& r0, uint32_t& r1, uint32_t& r2, uint32_t& r3,
                                       uint32_t a) {
    asm volatile("ldmatrix.sync.aligned.m8n8.x4.trans.shared.b16 {%0,%1,%2,%3}, [%4];"
                 : "=r"(r0), "=r"(r1), "=r"(r2), "=r"(r3) : "r"(a));
}
__device__ __forceinline__ void mma16816(float* c, const uint32_t* a, uint32_t b0, uint32_t b1) {
    asm volatile(
        "mma.sync.aligned.m16n8k16.row.col.f32.f16.f16.f32 "
        "{%0,%1,%2,%3}, {%4,%5,%6,%7}, {%8,%9}, {%0,%1,%2,%3};"
        : "+f"(c[0]), "+f"(c[1]), "+f"(c[2]), "+f"(c[3])
        : "r"(a[0]), "r"(a[1]), "r"(a[2]), "r"(a[3]), "r"(b0), "r"(b1));
}

#define SWA(o) ((o) ^ (((o) >> 3) & 0x70))   // 128B-row swizzle (A tile)
#define SWB(o) ((o) ^ (((o) >> 4) & 0xF0))   // 256B-row swizzle (B tile)

// ---------------- kernels ----------------

// adj fp32 -> fp16 * 8192
__global__ void __launch_bounds__(256) k_convert(const float* __restrict__ adj) {
    size_t i = ((size_t)blockIdx.x * 256 + threadIdx.x) * 8;
    float4 a = *(const float4*)(adj + i);
    float4 b = *(const float4*)(adj + i + 4);
    __half2 h0 = __floats2half2_rn(a.x * 8192.f, a.y * 8192.f);
    __half2 h1 = __floats2half2_rn(a.z * 8192.f, a.w * 8192.f);
    __half2 h2 = __floats2half2_rn(b.x * 8192.f, b.y * 8192.f);
    __half2 h3 = __floats2half2_rn(b.z * 8192.f, b.w * 8192.f);
    uint4 o;
    o.x = *(uint32_t*)&h0; o.y = *(uint32_t*)&h1;
    o.z = *(uint32_t*)&h2; o.w = *(uint32_t*)&h3;
    *(uint4*)(&g_adj16[i]) = o;
}

// x_m -> out sec0 + g_H ; mask -> out sec3
__global__ void __launch_bounds__(256) k_mask(const float* __restrict__ x,
                                              const float* __restrict__ mask,
                                              const float* __restrict__ noise,
                                              float* __restrict__ out) {
    size_t g = ((size_t)blockIdx.x * 256 + threadIdx.x) * 4;
    float4 xv = *(const float4*)(x + g);
    float4 mv = *(const float4*)(mask + g);
    float4 nv = *(const float4*)(noise + g);
    float4 v;
    v.x = xv.x * (1.f - mv.x) + nv.x * mv.x;
    v.y = xv.y * (1.f - mv.y) + nv.y * mv.y;
    v.z = xv.z * (1.f - mv.z) + nv.z * mv.z;
    v.w = xv.w * (1.f - mv.w) + nv.w * mv.w;
    *(float4*)(out + g) = v;
    *(float4*)(out + 3 * (size_t)SEC + g) = mv;
    *(float4*)(g_H + g) = v;
}

// HW = BN(g_H) @ W in exact fp32 (BN affine applied inline while loading H);
// quantize to fp16 row-major g_B16. Also zeroes g_sums2[zero_par].
// 256 blocks x 32 rows; warp w -> cols w*16..+15, lane l -> row l.
__global__ void __launch_bounds__(256) k_hw(const float* __restrict__ W,
                                            const float* __restrict__ stats,  // g_sums2[prev] or null
                                            const float* __restrict__ gamma,
                                            const float* __restrict__ beta,
                                            int zero_par) {
    extern __shared__ float sm_hw[];
    float* Hs = sm_hw;              // [32][129]
    float* Ws = sm_hw + 32 * 129;   // [128][128]
    __shared__ float sa[128], st[128];
    int tid = threadIdx.x;
    int r0 = blockIdx.x * 32;
    if (blockIdx.x == 0) g_sums2[zero_par][tid] = 0.f;

    if (tid < 128) {
        if (stats) {
            const float inN = 1.f / 8192.f;
            float mu = stats[tid] * inN;
            float var = stats[128 + tid] * inN - mu * mu;
            float a = gamma[tid] * rsqrtf(var + 1e-5f);
            sa[tid] = a;
            st[tid] = beta[tid] - a * mu;
        } else {
            sa[tid] = 1.f; st[tid] = 0.f;
        }
    }
    __syncthreads();

#pragma unroll
    for (int j = 0; j < 4; j++) {             // H tile 32x128, BN affine inline
        int v = tid + j * 256;
        int row = v >> 5, c4 = (v & 31) * 4;
        float4 f = *(const float4*)(g_H + (size_t)(r0 + row) * 128 + c4);
        float* d = Hs + row * 129 + c4;
        d[0] = f.x * sa[c4 + 0] + st[c4 + 0];
        d[1] = f.y * sa[c4 + 1] + st[c4 + 1];
        d[2] = f.z * sa[c4 + 2] + st[c4 + 2];
        d[3] = f.w * sa[c4 + 3] + st[c4 + 3];
    }
#pragma unroll
    for (int j = 0; j < 16; j++)              // W 128x128
        ((float4*)Ws)[tid + j * 256] = ((const float4*)W)[tid + j * 256];
    __syncthreads();

    int l = tid & 31, w = tid >> 5, cw = w * 16;
    float acc[16];
#pragma unroll
    for (int j = 0; j < 16; j++) acc[j] = 0.f;

#pragma unroll 4
    for (int k = 0; k < 128; k++) {
        float a0 = Hs[l * 129 + k];
        const float4* wr = (const float4*)(Ws + k * 128 + cw);
#pragma unroll
        for (int q = 0; q < 4; q++) {
            float4 wv = wr[q];
            acc[q * 4 + 0] += a0 * wv.x; acc[q * 4 + 1] += a0 * wv.y;
            acc[q * 4 + 2] += a0 * wv.z; acc[q * 4 + 3] += a0 * wv.w;
        }
    }
    int rA = r0 + l;
#pragma unroll
    for (int j = 0; j < 8; j++) {
        int c0 = cw + 2 * j;
        *(__half2*)&g_B16[(size_t)rA * 128 + c0] = __floats2half2_rn(acc[2 * j], acc[2 * j + 1]);
    }
}

// Big GEMM: P = adj16 @ B16 ; z = prelu(P/8192 + bias) -> g_H or out.
// 128 CTAs x (M=64, N=128), 512 threads (16 warps, warp tile m32n16),
// K-chunks of 64, 3-stage cp.async pipeline (R3-proven skeleton),
// fused column stats via shuffle reduce after stores.
__global__ void __launch_bounds__(512) k_big(const float* __restrict__ bias,
                                             const float* __restrict__ alpha,
                                             float* __restrict__ outp, int to_out,
                                             int do_stats, int par) {
    extern __shared__ char smem[];
    uint32_t sb = smem_u32(smem);
    const int tid = threadIdx.x, w = tid >> 5, l = tid & 31;
    const int wm = w >> 3, wn = w & 7;     // 2x8 warp grid (m32 x n16 warp tiles)
    const int m0 = blockIdx.x * 64;
    const __half* Ag = g_adj16;
    const __half* Bg = g_B16;

    auto load_stage = [&](int slot, int t) {
        uint32_t as = sb + slot * 24576;
        uint32_t bs = as + 8192;
        {                                     // A: 64 rows x 128B (512 x cp16)
            int row = tid >> 3, u = tid & 7;
            const void* g = Ag + (size_t)(m0 + row) * NNODE + t * 64 + u * 8;
            uint32_t off = (uint32_t)(row * 128 + u * 16);
            cp16(as + SWA(off), g);
        }
#pragma unroll
        for (int i = 0; i < 2; i++) {         // B: 64 rows x 256B (1024 x cp16)
            int idx = tid + i * 512;
            int row = idx >> 4, u = idx & 15;
            const void* g = Bg + (size_t)(t * 64 + row) * 128 + u * 8;
            uint32_t off = (uint32_t)(row * 256 + u * 16);
            cp16(bs + SWB(off), g);
        }
    };

    float acc[2][2][4];
#pragma unroll
    for (int i = 0; i < 2; i++)
#pragma unroll
        for (int j = 0; j < 2; j++)
#pragma unroll
            for (int q = 0; q < 4; q++) acc[i][j][q] = 0.f;

    load_stage(0, 0); CP_COMMIT();
    load_stage(1, 1); CP_COMMIT();

    for (int t = 0; t < 128; ++t) {
        CP_WAIT1();
        __syncthreads();
        if (t + 2 < 128) load_stage((t + 2) % 3, t + 2);
        CP_COMMIT();

        uint32_t as = sb + (t % 3) * 24576;
        uint32_t bs = as + 8192;
#pragma unroll
        for (int kk = 0; kk < 4; kk++) {
            uint32_t a[2][4], b[4];
#pragma unroll
            for (int ti = 0; ti < 2; ti++) {
                int mrow = wm * 32 + ti * 16 + (l & 15);
                int kcol = kk * 16 + (l >> 4) * 8;
                uint32_t off = (uint32_t)(mrow * 128 + kcol * 2);
                ldsm4(a[ti][0], a[ti][1], a[ti][2], a[ti][3], as + SWA(off));
            }
            {
                int krow = kk * 16 + (l & 15);
                int ncol = wn * 16 + (l >> 4) * 8;
                uint32_t off = (uint32_t)(krow * 256 + ncol * 2);
                ldsm4t(b[0], b[1], b[2], b[3], bs + SWB(off));
            }
#pragma unroll
            for (int ti = 0; ti < 2; ti++)
#pragma unroll
                for (int nj = 0; nj < 2; nj++)
                    mma16816(acc[ti][nj], a[ti], b[2 * nj], b[2 * nj + 1]);
        }
        __syncthreads();
    }

    // epilogue: /8192 + bias + prelu (+ fused column stats)
    float al = alpha[0];
    const float s = 1.f / 8192.f;
    float* dst = to_out ? outp : g_H;
    float ls[2][2] = {{0, 0}, {0, 0}}, lq[2][2] = {{0, 0}, {0, 0}};  // [nj][parity]
#pragma unroll
    for (int ti = 0; ti < 2; ti++) {
        int row = m0 + wm * 32 + ti * 16 + (l >> 2);
#pragma unroll
        for (int nj = 0; nj < 2; nj++) {
            int col = wn * 16 + nj * 8 + (l & 3) * 2;
            float2 bb = *(const float2*)(bias + col);
            float v0 = acc[ti][nj][0] * s + bb.x;
            float v1 = acc[ti][nj][1] * s + bb.y;
            float v2 = acc[ti][nj][2] * s + bb.x;
            float v3 = acc[ti][nj][3] * s + bb.y;
            v0 = v0 >= 0.f ? v0 : al * v0;
            v1 = v1 >= 0.f ? v1 : al * v1;
            v2 = v2 >= 0.f ? v2 : al * v2;
            v3 = v3 >= 0.f ? v3 : al * v3;
            *(float2*)(dst + (size_t)row * 128 + col)       = make_float2(v0, v1);
            *(float2*)(dst + (size_t)(row + 8) * 128 + col) = make_float2(v2, v3);
            ls[nj][0] += v0 + v2;           lq[nj][0] += v0 * v0 + v2 * v2;
            ls[nj][1] += v1 + v3;           lq[nj][1] += v1 * v1 + v3 * v3;
        }
    }
    if (do_stats) {
        __syncthreads();                   // stage smem now reusable
        float* ss = (float*)smem;          // [0..127]=sum, [128..255]=sumsq
        if (tid < 256) ss[tid] = 0.f;
        __syncthreads();
        // reduce over the 8 lanes sharing the same (l&3): xor strides 4, 8, 16
#pragma unroll
        for (int d = 4; d < 32; d <<= 1) {
#pragma unroll
            for (int nj = 0; nj < 2; nj++)
#pragma unroll
                for (int p = 0; p < 2; p++) {
                    ls[nj][p] += __shfl_xor_sync(0xFFFFFFFFu, ls[nj][p], d);
                    lq[nj][p] += __shfl_xor_sync(0xFFFFFFFFu, lq[nj][p], d);
                }
        }
        if (l < 4) {
#pragma unroll
            for (int nj = 0; nj < 2; nj++)
#pragma unroll
                for (int p = 0; p < 2; p++) {
                    int col = wn * 16 + nj * 8 + l * 2 + p;
                    atomicAdd(&ss[col],       ls[nj][p]);
                    atomicAdd(&ss[128 + col], lq[nj][p]);
                }
        }
        __syncthreads();
        if (tid < 256) atomicAdd(&g_sums2[par][tid], ss[tid]);
    }
}

// Write normalized copy of g_H (BN affine from stats) to dst — used once for `encoded`.
__global__ void __launch_bounds__(256) k_writenorm(const float* __restrict__ stats,
                                                   const float* __restrict__ gamma,
                                                   const float* __restrict__ beta,
                                                   float* __restrict__ dst) {
    size_t base = ((size_t)blockIdx.x * 256 + threadIdx.x) * 4;
    int c = (int)(base & 127);
    const float inN = 1.f / 8192.f;
    float4 s4 = *(const float4*)(stats + c);
    float4 q4 = *(const float4*)(stats + 128 + c);
    float4 g4 = *(const float4*)(gamma + c);
    float4 b4 = *(const float4*)(beta + c);
    float mu, var, a0, a1, a2, a3, t0, t1, t2, t3;
    mu = s4.x * inN; var = q4.x * inN - mu * mu; a0 = g4.x * rsqrtf(var + 1e-5f); t0 = b4.x - a0 * mu;
    mu = s4.y * inN; var = q4.y * inN - mu * mu; a1 = g4.y * rsqrtf(var + 1e-5f); t1 = b4.y - a1 * mu;
    mu = s4.z * inN; var = q4.z * inN - mu * mu; a2 = g4.z * rsqrtf(var + 1e-5f); t2 = b4.z - a2 * mu;
    mu = s4.w * inN; var = q4.w * inN - mu * mu; a3 = g4.w * rsqrtf(var + 1e-5f); t3 = b4.w - a3 * mu;
    float4 v = *(const float4*)(g_H + base);
    v.x = v.x * a0 + t0; v.y = v.y * a1 + t1; v.z = v.z * a2 + t2; v.w = v.w * a3 + t3;
    *(float4*)(dst + base) = v;
}

// ---------------- launch ----------------
extern "C" void kernel_launch(void* const* d_in, const int* in_sizes, int n_in,
                              void* d_out, int out_size) {
    const float* x     = (const float*)d_in[0];
    const float* adj   = (const float*)d_in[1];
    const float* mask  = (const float*)d_in[2];
    const float* noise = (const float*)d_in[3];
    const float* eW = (const float*)d_in[4];
    const float* eb = (const float*)d_in[5];
    const float* ea = (const float*)d_in[6];
    const float* eg = (const float*)d_in[7];
    const float* eB = (const float*)d_in[8];
    const float* dW = (const float*)d_in[9];
    const float* db = (const float*)d_in[10];
    const float* da = (const float*)d_in[11];
    const float* dg = (const float*)d_in[12];
    const float* dB = (const float*)d_in[13];
    float* out = (float*)d_out;

    const int SMEM_BIG = 3 * 24576;                   // 73728
    const int SMEM_HW  = (32 * 129 + 128 * 128) * 4;  // 82048
    cudaFuncSetAttribute(k_big, cudaFuncAttributeMaxDynamicSharedMemorySize, SMEM_BIG);
    cudaFuncSetAttribute(k_hw,  cudaFuncAttributeMaxDynamicSharedMemorySize, SMEM_HW);

    // device pointers to the ping-pong stats buffers (constant addresses)
    float* d_sums0 = nullptr; float* d_sums1 = nullptr;
    cudaGetSymbolAddress((void**)&d_sums0, g_sums2);
    d_sums1 = d_sums0 + 2 * DFEAT;
    const float* sums[2] = {d_sums0, d_sums1};

    k_convert<<<32768, 256>>>(adj);
    k_mask<<<1024, 256>>>(x, mask, noise, out);

    // ---- encoder: 5 x (GCN with inline BN-of-previous -> stats) ----
    // layer j (global 0..9): k_hw reads stats[(j-1)&1] (null for j=0), zeroes [(j)&1];
    // k_big writes stats[(j)&1].
    for (int i = 0; i < 5; i++) {
        const float* prev_stats = (i == 0) ? nullptr : sums[(i - 1) & 1];
        const float* prev_g = (i == 0) ? nullptr : eg + (i - 1) * 128;
        const float* prev_b = (i == 0) ? nullptr : eB + (i - 1) * 128;
        k_hw<<<256, 256, SMEM_HW>>>(eW + (size_t)i * 16384, prev_stats, prev_g, prev_b, i & 1);
        k_big<<<128, 512, SMEM_BIG>>>(eb + i * 128, ea + i, out, 0, 1, i & 1);
    }
    // encoded = BN(enc layer 5 output)  (stats par 0, enc gamma/beta[4])
    k_writenorm<<<1024, 256>>>(sums[0], eg + 4 * 128, eB + 4 * 128, out + (size_t)SEC);

    // ---- decoder ----
    // dec layer 0 (global j=5): input BN uses enc[4] params + stats par 0
    k_hw<<<256, 256, SMEM_HW>>>(dW, sums[0], eg + 4 * 128, eB + 4 * 128, 1);
    k_big<<<128, 512, SMEM_BIG>>>(db, da, out, 0, 1, 1);
    // dec layers 1..3 (global j=6..8)
    for (int i = 1; i < 4; i++) {
        int j = 5 + i;
        k_hw<<<256, 256, SMEM_HW>>>(dW + (size_t)i * 16384, sums[(j - 1) & 1],
                                    dg + (i - 1) * 128, dB + (i - 1) * 128, j & 1);
        k_big<<<128, 512, SMEM_BIG>>>(db + i * 128, da + i, out, 0, 1, j & 1);
    }
    // dec layer 4 (global j=9): BN of dec layer 3, final GCN straight to out sec 2, no stats
    k_hw<<<256, 256, SMEM_HW>>>(dW + (size_t)4 * 16384, sums[0], dg + 3 * 128, dB + 3 * 128, 1);
    k_big<<<128, 512, SMEM_BIG>>>(db + 4 * 128, da + 4, out + 2 * (size_t)SEC, 1, 0, 1);
}

// round 6
// speedup vs baseline: 1.2637x; 1.2637x over previous
#include <cuda_runtime.h>
#include <cuda_fp16.h>
#include <cstdint>
#include <cstddef>

#define NNODE 8192
#define DFEAT 128
#define SEC   1048576  // 8192*128

// ---------------- scratch (allocation-free __device__ globals) ----------------
__device__ __align__(16) __half g_adj16[(size_t)NNODE * NNODE]; // adj*8192 fp16 (128 MB)
__device__ __align__(16) __half g_B16[(size_t)NNODE * DFEAT];   // (h@W) fp16 row-major (2 MB)
__device__ __align__(16) float  g_H[(size_t)NNODE * DFEAT];     // raw PReLU output fp32 (4 MB)
__device__ __align__(16) float  g_sums2[2][2 * DFEAT];          // ping-pong col sum / sumsq

// ---------------- baseline-PTX helpers (sm_80-era; safe on .target sm_103) --------
__device__ __forceinline__ uint32_t smem_u32(const void* p) {
    uint32_t a;
    asm("{ .reg .u64 t; cvta.to.shared.u64 t, %1; cvt.u32.u64 %0, t; }" : "=r"(a) : "l"(p));
    return a;
}
__device__ __forceinline__ void cp16(uint32_t saddr, const void* gaddr) {
    asm volatile("cp.async.cg.shared.global [%0], [%1], 16;" :: "r"(saddr), "l"(gaddr));
}
#define CP_COMMIT() asm volatile("cp.async.commit_group;" ::: "memory")
#define CP_WAIT1()  asm volatile("cp.async.wait_group 1;" ::: "memory")

__device__ __forceinline__ void ldsm4(uint32_t* r, uint32_t a) {
    asm volatile("ldmatrix.sync.aligned.m8n8.x4.shared.b16 {%0,%1,%2,%3}, [%4];"
                 : "=r"(r[0]), "=r"(r[1]), "=r"(r[2]), "=r"(r[3]) : "r"(a));
}
__device__ __forceinline__ void ldsm4t(uint32_t* r, uint32_t a) {
    asm volatile("ldmatrix.sync.aligned.m8n8.x4.trans.shared.b16 {%0,%1,%2,%3}, [%4];"
                 : "=r"(r[0]), "=r"(r[1]), "=r"(r[2]), "=r"(r[3]) : "r"(a));
}
__device__ __forceinline__ void mma16816(float* c, const uint32_t* a, uint32_t b0, uint32_t b1) {
    asm volatile(
        "mma.sync.aligned.m16n8k16.row.col.f32.f16.f16.f32 "
        "{%0,%1,%2,%3}, {%4,%5,%6,%7}, {%8,%9}, {%0,%1,%2,%3};"
        : "+f"(c[0]), "+f"(c[1]), "+f"(c[2]), "+f"(c[3])
        : "r"(a[0]), "r"(a[1]), "r"(a[2]), "r"(a[3]), "r"(b0), "r"(b1));
}

#define SWA(o) ((o) ^ (((o) >> 3) & 0x70))   // 128B-row swizzle (A tile)
#define SWB(o) ((o) ^ (((o) >> 4) & 0xF0))   // 256B-row swizzle (B tile)

// packed fp32x2 FMA helpers (bitwise-identical per-scalar chains)
__device__ __forceinline__ void fma2(uint64_t& d, uint64_t a, uint64_t b) {
    asm("fma.rn.f32x2 %0, %1, %2, %3;" : "=l"(d) : "l"(a), "l"(b), "l"(d));
}
__device__ __forceinline__ uint64_t dup2(float x) {
    uint64_t r; asm("mov.b64 %0, {%1, %1};" : "=l"(r) : "f"(x)); return r;
}
__device__ __forceinline__ float2 unp2(uint64_t v) {
    float2 r; asm("mov.b64 {%0, %1}, %2;" : "=f"(r.x), "=f"(r.y) : "l"(v)); return r;
}

// ---------------- kernels ----------------

// adj fp32 -> fp16 * 8192
__global__ void __launch_bounds__(256) k_convert(const float* __restrict__ adj) {
    size_t i = ((size_t)blockIdx.x * 256 + threadIdx.x) * 8;
    float4 a = *(const float4*)(adj + i);
    float4 b = *(const float4*)(adj + i + 4);
    __half2 h0 = __floats2half2_rn(a.x * 8192.f, a.y * 8192.f);
    __half2 h1 = __floats2half2_rn(a.z * 8192.f, a.w * 8192.f);
    __half2 h2 = __floats2half2_rn(b.x * 8192.f, b.y * 8192.f);
    __half2 h3 = __floats2half2_rn(b.z * 8192.f, b.w * 8192.f);
    uint4 o;
    o.x = *(uint32_t*)&h0; o.y = *(uint32_t*)&h1;
    o.z = *(uint32_t*)&h2; o.w = *(uint32_t*)&h3;
    *(uint4*)(&g_adj16[i]) = o;
}

// x_m -> out sec0 + g_H ; mask -> out sec3
__global__ void __launch_bounds__(256) k_mask(const float* __restrict__ x,
                                              const float* __restrict__ mask,
                                              const float* __restrict__ noise,
                                              float* __restrict__ out) {
    size_t g = ((size_t)blockIdx.x * 256 + threadIdx.x) * 4;
    float4 xv = *(const float4*)(x + g);
    float4 mv = *(const float4*)(mask + g);
    float4 nv = *(const float4*)(noise + g);
    float4 v;
    v.x = xv.x * (1.f - mv.x) + nv.x * mv.x;
    v.y = xv.y * (1.f - mv.y) + nv.y * mv.y;
    v.z = xv.z * (1.f - mv.z) + nv.z * mv.z;
    v.w = xv.w * (1.f - mv.w) + nv.w * mv.w;
    *(float4*)(out + g) = v;
    *(float4*)(out + 3 * (size_t)SEC + g) = mv;
    *(float4*)(g_H + g) = v;
}

// HW = BN(g_H) @ W in exact fp32 (BN affine inline while loading H; f32x2 FMA);
// quantize to fp16 row-major g_B16. Also zeroes g_sums2[zero_par].
__global__ void __launch_bounds__(256) k_hw(const float* __restrict__ W,
                                            const float* __restrict__ stats,
                                            const float* __restrict__ gamma,
                                            const float* __restrict__ beta,
                                            int zero_par) {
    extern __shared__ float sm_hw[];
    float* Hs = sm_hw;              // [32][129]
    float* Ws = sm_hw + 32 * 129;   // [128][128]
    __shared__ float sa[128], st[128];
    int tid = threadIdx.x;
    int r0 = blockIdx.x * 32;
    if (blockIdx.x == 0) g_sums2[zero_par][tid] = 0.f;

    if (tid < 128) {
        if (stats) {
            const float inN = 1.f / 8192.f;
            float mu = stats[tid] * inN;
            float var = stats[128 + tid] * inN - mu * mu;
            float a = gamma[tid] * rsqrtf(var + 1e-5f);
            sa[tid] = a;
            st[tid] = beta[tid] - a * mu;
        } else {
            sa[tid] = 1.f; st[tid] = 0.f;
        }
    }
    __syncthreads();

#pragma unroll
    for (int j = 0; j < 4; j++) {             // H tile 32x128, BN affine inline
        int v = tid + j * 256;
        int row = v >> 5, c4 = (v & 31) * 4;
        float4 f = *(const float4*)(g_H + (size_t)(r0 + row) * 128 + c4);
        float* d = Hs + row * 129 + c4;
        d[0] = f.x * sa[c4 + 0] + st[c4 + 0];
        d[1] = f.y * sa[c4 + 1] + st[c4 + 1];
        d[2] = f.z * sa[c4 + 2] + st[c4 + 2];
        d[3] = f.w * sa[c4 + 3] + st[c4 + 3];
    }
#pragma unroll
    for (int j = 0; j < 16; j++)              // W 128x128
        ((float4*)Ws)[tid + j * 256] = ((const float4*)W)[tid + j * 256];
    __syncthreads();

    int l = tid & 31, w = tid >> 5, cw = w * 16;
    uint64_t acc2[8];
#pragma unroll
    for (int j = 0; j < 8; j++) acc2[j] = 0ull;

#pragma unroll 4
    for (int k = 0; k < 128; k++) {
        uint64_t a0 = dup2(Hs[l * 129 + k]);
        const uint64_t* wr = (const uint64_t*)(Ws + k * 128 + cw);
#pragma unroll
        for (int q = 0; q < 8; q++) fma2(acc2[q], a0, wr[q]);
    }
    int rA = r0 + l;
#pragma unroll
    for (int j = 0; j < 8; j++) {
        float2 va = unp2(acc2[j]);
        *(__half2*)&g_B16[(size_t)rA * 128 + cw + 2 * j] = __floats2half2_rn(va.x, va.y);
    }
}

// Big GEMM: P = adj16 @ B16 ; z = prelu(P/8192 + bias) -> g_H or out.
// 256 CTAs x (M=32, N=128), 128 threads (4 warps m32n32), 2 CTAs/SM,
// K-chunks of 64, 3-stage cp.async pipeline, fragment double-buffer,
// fused column stats via shuffle + direct smem stores.
__global__ void __launch_bounds__(128) k_big(const float* __restrict__ bias,
                                             const float* __restrict__ alpha,
                                             float* __restrict__ outp, int to_out,
                                             int do_stats, int par) {
    extern __shared__ char smem[];
    uint32_t sb = smem_u32(smem);
    const int tid = threadIdx.x, w = tid >> 5, l = tid & 31;   // w = wn (0..3)
    const int m0 = blockIdx.x * 32;
    const __half* Ag = g_adj16;
    const __half* Bg = g_B16;
    const int STAGE = 20480;   // A 4KB + B 16KB

    auto load_stage = [&](int slot, int t) {
        uint32_t as = sb + slot * STAGE;
        uint32_t bs = as + 4096;
#pragma unroll
        for (int i = 0; i < 2; i++) {          // A: 32 rows x 128B (256 cp16)
            int idx = tid + i * 128;
            int row = idx >> 3, u = idx & 7;
            const void* g = Ag + (size_t)(m0 + row) * NNODE + t * 64 + u * 8;
            uint32_t off = (uint32_t)(row * 128 + u * 16);
            cp16(as + SWA(off), g);
        }
#pragma unroll
        for (int i = 0; i < 8; i++) {          // B: 64 rows x 256B (1024 cp16)
            int idx = tid + i * 128;
            int row = idx >> 4, u = idx & 15;
            const void* g = Bg + (size_t)(t * 64 + row) * 128 + u * 8;
            uint32_t off = (uint32_t)(row * 256 + u * 16);
            cp16(bs + SWB(off), g);
        }
    };

    float acc[2][4][4];
#pragma unroll
    for (int i = 0; i < 2; i++)
#pragma unroll
        for (int j = 0; j < 4; j++)
#pragma unroll
            for (int q = 0; q < 4; q++) acc[i][j][q] = 0.f;

    uint32_t afr[2][2][4], bfr[2][2][4];
    auto load_frags = [&](uint32_t as, uint32_t bs, int kk, int fb) {
#pragma unroll
        for (int ti = 0; ti < 2; ti++) {
            int mrow = ti * 16 + (l & 15);
            int kcol = kk * 16 + (l >> 4) * 8;
            ldsm4(afr[fb][ti], as + SWA((uint32_t)(mrow * 128 + kcol * 2)));
        }
#pragma unroll
        for (int tj2 = 0; tj2 < 2; tj2++) {
            int krow = kk * 16 + (l & 15);
            int ncol = w * 32 + tj2 * 16 + (l >> 4) * 8;
            ldsm4t(bfr[fb][tj2], bs + SWB((uint32_t)(krow * 256 + ncol * 2)));
        }
    };

    load_stage(0, 0); CP_COMMIT();
    load_stage(1, 1); CP_COMMIT();

    for (int t = 0; t < 128; ++t) {
        CP_WAIT1();
        __syncthreads();
        if (t + 2 < 128) load_stage((t + 2) % 3, t + 2);
        CP_COMMIT();

        uint32_t as = sb + (t % 3) * STAGE;
        uint32_t bs = as + 4096;
        load_frags(as, bs, 0, 0);
#pragma unroll
        for (int kk = 0; kk < 4; kk++) {
            int fb = kk & 1;
            if (kk < 3) load_frags(as, bs, kk + 1, fb ^ 1);
#pragma unroll
            for (int ti = 0; ti < 2; ti++)
#pragma unroll
                for (int tj = 0; tj < 4; tj++)
                    mma16816(acc[ti][tj], afr[fb][ti],
                             bfr[fb][tj >> 1][2 * (tj & 1)],
                             bfr[fb][tj >> 1][2 * (tj & 1) + 1]);
        }
        __syncthreads();
    }

    // epilogue: /8192 + bias + prelu (+ fused column stats)
    float al = alpha[0];
    const float s = 1.f / 8192.f;
    float* dst = to_out ? outp : g_H;
    float ls[4][2] = {{0,0},{0,0},{0,0},{0,0}};
    float lq[4][2] = {{0,0},{0,0},{0,0},{0,0}};
#pragma unroll
    for (int ti = 0; ti < 2; ti++) {
        int row = m0 + ti * 16 + (l >> 2);
#pragma unroll
        for (int tj = 0; tj < 4; tj++) {
            int col = w * 32 + tj * 8 + (l & 3) * 2;
            float2 bb = *(const float2*)(bias + col);
            float v0 = acc[ti][tj][0] * s + bb.x;
            float v1 = acc[ti][tj][1] * s + bb.y;
            float v2 = acc[ti][tj][2] * s + bb.x;
            float v3 = acc[ti][tj][3] * s + bb.y;
            v0 = v0 >= 0.f ? v0 : al * v0;
            v1 = v1 >= 0.f ? v1 : al * v1;
            v2 = v2 >= 0.f ? v2 : al * v2;
            v3 = v3 >= 0.f ? v3 : al * v3;
            *(float2*)(dst + (size_t)row * 128 + col)       = make_float2(v0, v1);
            *(float2*)(dst + (size_t)(row + 8) * 128 + col) = make_float2(v2, v3);
            ls[tj][0] += v0 + v2;  lq[tj][0] += v0 * v0 + v2 * v2;
            ls[tj][1] += v1 + v3;  lq[tj][1] += v1 * v1 + v3 * v3;
        }
    }
    if (do_stats) {
        __syncthreads();                   // stage smem now reusable
        float* ss = (float*)smem;          // [0..127]=sum, [128..255]=sumsq
        // reduce over the 8 lanes sharing (l&3): xor strides 4, 8, 16
#pragma unroll
        for (int d = 4; d < 32; d <<= 1) {
#pragma unroll
            for (int tj = 0; tj < 4; tj++)
#pragma unroll
                for (int p = 0; p < 2; p++) {
                    ls[tj][p] += __shfl_xor_sync(0xFFFFFFFFu, ls[tj][p], d);
                    lq[tj][p] += __shfl_xor_sync(0xFFFFFFFFu, lq[tj][p], d);
                }
        }
        if (l < 4) {
            // each (warp, lane<4, tj, p) owns a unique column -> direct stores
#pragma unroll
            for (int tj = 0; tj < 4; tj++)
#pragma unroll
                for (int p = 0; p < 2; p++) {
                    int col = w * 32 + tj * 8 + l * 2 + p;
                    ss[col]       = ls[tj][p];
                    ss[128 + col] = lq[tj][p];
                }
        }
        __syncthreads();
        atomicAdd(&g_sums2[par][tid],       ss[tid]);
        atomicAdd(&g_sums2[par][tid + 128], ss[tid + 128]);
    }
}

// Write normalized copy of g_H (BN affine from stats) to dst — used once for `encoded`.
__global__ void __launch_bounds__(256) k_writenorm(const float* __restrict__ stats,
                                                   const float* __restrict__ gamma,
                                                   const float* __restrict__ beta,
                                                   float* __restrict__ dst) {
    size_t base = ((size_t)blockIdx.x * 256 + threadIdx.x) * 4;
    int c = (int)(base & 127);
    const float inN = 1.f / 8192.f;
    float4 s4 = *(const float4*)(stats + c);
    float4 q4 = *(const float4*)(stats + 128 + c);
    float4 g4 = *(const float4*)(gamma + c);
    float4 b4 = *(const float4*)(beta + c);
    float mu, var, a0, a1, a2, a3, t0, t1, t2, t3;
    mu = s4.x * inN; var = q4.x * inN - mu * mu; a0 = g4.x * rsqrtf(var + 1e-5f); t0 = b4.x - a0 * mu;
    mu = s4.y * inN; var = q4.y * inN - mu * mu; a1 = g4.y * rsqrtf(var + 1e-5f); t1 = b4.y - a1 * mu;
    mu = s4.z * inN; var = q4.z * inN - mu * mu; a2 = g4.z * rsqrtf(var + 1e-5f); t2 = b4.z - a2 * mu;
    mu = s4.w * inN; var = q4.w * inN - mu * mu; a3 = g4.w * rsqrtf(var + 1e-5f); t3 = b4.w - a3 * mu;
    float4 v = *(const float4*)(g_H + base);
    v.x = v.x * a0 + t0; v.y = v.y * a1 + t1; v.z = v.z * a2 + t2; v.w = v.w * a3 + t3;
    *(float4*)(dst + base) = v;
}

// ---------------- launch ----------------
extern "C" void kernel_launch(void* const* d_in, const int* in_sizes, int n_in,
                              void* d_out, int out_size) {
    const float* x     = (const float*)d_in[0];
    const float* adj   = (const float*)d_in[1];
    const float* mask  = (const float*)d_in[2];
    const float* noise = (const float*)d_in[3];
    const float* eW = (const float*)d_in[4];
    const float* eb = (const float*)d_in[5];
    const float* ea = (const float*)d_in[6];
    const float* eg = (const float*)d_in[7];
    const float* eB = (const float*)d_in[8];
    const float* dW = (const float*)d_in[9];
    const float* db = (const float*)d_in[10];
    const float* da = (const float*)d_in[11];
    const float* dg = (const float*)d_in[12];
    const float* dB = (const float*)d_in[13];
    float* out = (float*)d_out;

    const int SMEM_BIG = 3 * 20480;                   // 61440
    const int SMEM_HW  = (32 * 129 + 128 * 128) * 4;  // 82048
    cudaFuncSetAttribute(k_big, cudaFuncAttributeMaxDynamicSharedMemorySize, SMEM_BIG);
    cudaFuncSetAttribute(k_hw,  cudaFuncAttributeMaxDynamicSharedMemorySize, SMEM_HW);

    float* d_sums0 = nullptr; float* d_sums1 = nullptr;
    cudaGetSymbolAddress((void**)&d_sums0, g_sums2);
    d_sums1 = d_sums0 + 2 * DFEAT;
    const float* sums[2] = {d_sums0, d_sums1};

    k_convert<<<32768, 256>>>(adj);
    k_mask<<<1024, 256>>>(x, mask, noise, out);

    // ---- encoder: 5 x (GCN with inline BN-of-previous) ----
    for (int i = 0; i < 5; i++) {
        const float* prev_stats = (i == 0) ? nullptr : sums[(i - 1) & 1];
        const float* prev_g = (i == 0) ? nullptr : eg + (i - 1) * 128;
        const float* prev_b = (i == 0) ? nullptr : eB + (i - 1) * 128;
        k_hw<<<256, 256, SMEM_HW>>>(eW + (size_t)i * 16384, prev_stats, prev_g, prev_b, i & 1);
        k_big<<<256, 128, SMEM_BIG>>>(eb + i * 128, ea + i, out, 0, 1, i & 1);
    }
    // encoded = BN(enc layer 5 output)
    k_writenorm<<<1024, 256>>>(sums[0], eg + 4 * 128, eB + 4 * 128, out + (size_t)SEC);

    // ---- decoder ----
    k_hw<<<256, 256, SMEM_HW>>>(dW, sums[0], eg + 4 * 128, eB + 4 * 128, 1);
    k_big<<<256, 128, SMEM_BIG>>>(db, da, out, 0, 1, 1);
    for (int i = 1; i < 4; i++) {
        int j = 5 + i;
        k_hw<<<256, 256, SMEM_HW>>>(dW + (size_t)i * 16384, sums[(j - 1) & 1],
                                    dg + (i - 1) * 128, dB + (i - 1) * 128, j & 1);
        k_big<<<256, 128, SMEM_BIG>>>(db + i * 128, da + i, out, 0, 1, j & 1);
    }
    k_hw<<<256, 256, SMEM_HW>>>(dW + (size_t)4 * 16384, sums[0], dg + 3 * 128, dB + 3 * 128, 1);
    k_big<<<256, 128, SMEM_BIG>>>(db + 4 * 128, da + 4, out + 2 * (size_t)SEC, 1, 0, 1);
}